// round 11
// baseline (speedup 1.0000x reference)
#include <cuda_runtime.h>
#include <cstdint>

#define BATCH   8192
#define FEAT    128
#define DEG     32
#define KSEL    16
#define EMB     128

// ---------------- scratch (static device arrays; no allocation) ----------------
__device__ float g_xbuf[BATCH * FEAT];          // self feats   [B,128]
__device__ float g_agg [3 * BATCH * FEAT];      // agg feats    [3,B,128]

// ---------------- f32x2 packed-FMA helpers (Blackwell FFMA2 via PTX) ----------------
__device__ __forceinline__ unsigned long long pk2(float x, float y) {
    unsigned int xu = __float_as_uint(x), yu = __float_as_uint(y);
    unsigned long long r;
    asm("mov.b64 %0, {%1, %2};" : "=l"(r) : "r"(xu), "r"(yu));
    return r;
}
__device__ __forceinline__ void upk2(unsigned long long v, float& x, float& y) {
    unsigned int lo, hi;
    asm("mov.b64 {%0, %1}, %2;" : "=r"(lo), "=r"(hi) : "l"(v));
    x = __uint_as_float(lo);
    y = __uint_as_float(hi);
}
__device__ __forceinline__ void ffma2(unsigned long long& d,
                                      unsigned long long a,
                                      unsigned long long b) {
    asm("fma.rn.f32x2 %0, %1, %2, %0;" : "+l"(d) : "l"(a), "l"(b));
}

// ---------------- Kernel B (launched FIRST): gather + score + top-K + mean ----------------
// One block per (b, rel), 128 threads. Rows live in REGISTERS end-to-end:
// gather -> score (register dot + butterfly) -> select -> per-warp register
// reduction of selected rows -> tiny smem combine. cs0 computed locally
// (removes dependency on kernel A so this can launch first).
__global__ __launch_bounds__(128) void agg_kernel(const float* __restrict__ feat,
                                                  const float* __restrict__ Wclf,
                                                  const float* __restrict__ bclf,
                                                  const int*   __restrict__ nodes,
                                                  const int*   __restrict__ n1,
                                                  const int*   __restrict__ n2,
                                                  const int*   __restrict__ n3) {
    const int b   = blockIdx.x;
    const int rel = blockIdx.y;
    const int* nb = (rel == 0) ? n1 : (rel == 1) ? n2 : n3;

    // 16-byte alignment REQUIRED: spart receives STS.128 (misaligned-address
    // trap in R9 came from the compiler placing this at a 4-mod-16 offset).
    __shared__ __align__(16) float spart[4][132];
    __shared__ float    sscore[DEG];
    __shared__ float    scs0;
    __shared__ unsigned smask;

    const int t = threadIdx.x;
    const int w = t >> 5, l = t & 31;

    // W_clf column-0 pieces for this lane's float4 slot (rows 4l..4l+3)
    float w00 = __ldg(Wclf + 8 * l);
    float w01 = __ldg(Wclf + 8 * l + 2);
    float w02 = __ldg(Wclf + 8 * l + 4);
    float w03 = __ldg(Wclf + 8 * l + 6);
    float bias0 = __ldg(bclf);

    // phase 1: all indices, then all rows — maximal MLP
    int nidx[8];
    #pragma unroll
    for (int r = 0; r < 8; r++)
        nidx[r] = __ldg(nb + b * DEG + w + 4 * r);
    float4 cf;
    if (w == 0) {
        long cb = (long)__ldg(nodes + b) * FEAT;
        cf = __ldg((const float4*)(feat + cb) + l);
    }
    float4 f[8];
    #pragma unroll
    for (int r = 0; r < 8; r++)
        f[r] = __ldg((const float4*)(feat + (long)nidx[r] * FEAT) + l);

    // phase 2: per-lane partial dots, interleaved butterfly reductions
    float p[8];
    #pragma unroll
    for (int r = 0; r < 8; r++)
        p[r] = f[r].x * w00 + f[r].y * w01 + f[r].z * w02 + f[r].w * w03;
    #pragma unroll
    for (int o = 16; o; o >>= 1) {
        #pragma unroll
        for (int r = 0; r < 8; r++)
            p[r] += __shfl_xor_sync(0xffffffffu, p[r], o);
    }
    if (l == 0) {
        #pragma unroll
        for (int r = 0; r < 8; r++)
            sscore[w + 4 * r] = p[r] + bias0;
    }
    if (w == 0) {
        // center score, same FMA shape/order as kernel A -> same rounding
        float pc = cf.x * w00 + cf.y * w01 + cf.z * w02 + cf.w * w03;
        #pragma unroll
        for (int o = 16; o; o >>= 1) pc += __shfl_xor_sync(0xffffffffu, pc, o);
        if (l == 0) scs0 = pc + bias0;
    }
    __syncthreads();

    // rank-based selection of the K smallest |score - cs0| (index tiebreak
    // matches jax.lax.top_k's stable lower-index-first semantics)
    if (t < DEG) {
        float cs0 = scs0;
        float di = fabsf(sscore[t] - cs0);
        int rank = 0;
        #pragma unroll
        for (int j = 0; j < DEG; j++) {
            float dj = fabsf(sscore[j] - cs0);
            rank += (dj < di) || (dj == di && j < t);
        }
        unsigned m = __ballot_sync(0xffffffffu, rank < KSEL);
        if (t == 0) smask = m;
    }
    __syncthreads();

    // per-warp register reduction of its selected rows
    const unsigned m = smask;
    float4 acc = make_float4(0.f, 0.f, 0.f, 0.f);
    #pragma unroll
    for (int r = 0; r < 8; r++) {
        if (m & (1u << (w + 4 * r))) {
            acc.x += f[r].x; acc.y += f[r].y; acc.z += f[r].z; acc.w += f[r].w;
        }
    }
    *(float4*)&spart[w][4 * l] = acc;
    __syncthreads();

    // combine 4 warp partials; coalesced 512B store
    float s = spart[0][t] + spart[1][t] + spart[2][t] + spart[3][t];
    g_agg[((long)rel * BATCH + b) * FEAT + t] = s * (1.0f / KSEL);
}

// ---------------- Kernel A: self gather + center scores (1 warp per node) ----------------
__global__ __launch_bounds__(256) void self_score_kernel(const float* __restrict__ feat,
                                                         const float* __restrict__ Wclf,
                                                         const float* __restrict__ bclf,
                                                         const int*   __restrict__ nodes,
                                                         float* __restrict__ out_cs) {
    int wg = threadIdx.x >> 5, l = threadIdx.x & 31;
    int b = blockIdx.x * 8 + wg;
    long base = (long)__ldg(nodes + b) * FEAT;
    float4 f = __ldg((const float4*)(feat + base) + l);
    *(float4*)(g_xbuf + b * FEAT + 4 * l) = f;
    float4 wAB0 = __ldg((const float4*)Wclf + 2 * l);
    float4 wAB1 = __ldg((const float4*)Wclf + 2 * l + 1);
    float p0 = f.x * wAB0.x + f.y * wAB0.z + f.z * wAB1.x + f.w * wAB1.z;
    float p1 = f.x * wAB0.y + f.y * wAB0.w + f.z * wAB1.y + f.w * wAB1.w;
    #pragma unroll
    for (int o = 16; o; o >>= 1) {
        p0 += __shfl_xor_sync(0xffffffffu, p0, o);
        p1 += __shfl_xor_sync(0xffffffffu, p1, o);
    }
    if (l == 0) {
        out_cs[b * 2]     = p0 + __ldg(bclf);
        out_cs[b * 2 + 1] = p1 + __ldg(bclf + 1);
    }
}

// ---------------- Kernel C: fused 3x intra GEMM + comb GEMM + relu + transpose ----------------
// 128 blocks, BM=64, 512 threads (4 warps/SMSP for latency hiding).
// A-tiles smem-resident; W double-buffered with register prefetch.
// Inner product: packed f32x2 FMA (FFMA2); micro-tile 2 rows x 8 cols.

#define APITCH 132   // smem row pitch (floats); 528B rows keep float4 slots 16B-aligned

__device__ __forceinline__ void mma_chunk(const float* __restrict__ A,
                                          const float* __restrict__ sW,
                                          int c0, unsigned long long acc[2][4]) {
    #pragma unroll
    for (int q = 0; q < 4; q++) {
        float4 a0 = *(const float4*)&A[0 * APITCH + 4 * q];
        float4 a1 = *(const float4*)&A[1 * APITCH + 4 * q];
        float av0[4] = {a0.x, a0.y, a0.z, a0.w};
        float av1[4] = {a1.x, a1.y, a1.z, a1.w};
        #pragma unroll
        for (int k = 0; k < 4; k++) {
            int k2 = 4 * q + k;
            ulonglong2 b01 = *(const ulonglong2*)&sW[k2 * 128 + c0];
            ulonglong2 b23 = *(const ulonglong2*)&sW[k2 * 128 + c0 + 4];
            unsigned long long ap;
            ap = pk2(av0[k], av0[k]);
            ffma2(acc[0][0], ap, b01.x); ffma2(acc[0][1], ap, b01.y);
            ffma2(acc[0][2], ap, b23.x); ffma2(acc[0][3], ap, b23.y);
            ap = pk2(av1[k], av1[k]);
            ffma2(acc[1][0], ap, b01.x); ffma2(acc[1][1], ap, b01.y);
            ffma2(acc[1][2], ap, b23.x); ffma2(acc[1][3], ap, b23.y);
        }
    }
}

__global__ __launch_bounds__(512, 1) void fused_gemm_kernel(const float* __restrict__ Wi1,
                                                            const float* __restrict__ Wi2,
                                                            const float* __restrict__ Wi3,
                                                            const float* __restrict__ Wc,
                                                            float* __restrict__ out) {
    extern __shared__ __align__(16) float smem[];
    float* sSelf = smem;                               // 64*APITCH
    float* sAgg0 = smem + 64 * APITCH;
    float* sAgg1 = smem + 2 * 64 * APITCH;
    float* sAgg2 = smem + 3 * 64 * APITCH;
    float* sWb0  = smem + 4 * 64 * APITCH;             // 16*128 double buffer
    float* sWb1  = sWb0 + 16 * 128;
    float* sAggs[3] = {sAgg0, sAgg1, sAgg2};
    float* sWbuf[2] = {sWb0, sWb1};

    const int tid = threadIdx.x;
    const int bm  = blockIdx.x * 64;

    // load self + agg tiles (64x128 each) — 4 float4 per thread per tile
    #pragma unroll
    for (int i = 0; i < 4; i++) {
        int e = tid + i * 512;        // float4 index
        int row = e >> 5;
        int c4  = e & 31;
        float4 v = __ldg((const float4*)(g_xbuf + (long)(bm + row) * FEAT) + c4);
        *(float4*)&sSelf[row * APITCH + c4 * 4] = v;
    }
    #pragma unroll
    for (int rel = 0; rel < 3; rel++) {
        #pragma unroll
        for (int i = 0; i < 4; i++) {
            int e = tid + i * 512;
            int row = e >> 5;
            int c4  = e & 31;
            float4 v = __ldg((const float4*)(g_agg + ((long)rel * BATCH + bm + row) * FEAT) + c4);
            *(float4*)&sAggs[rel][row * APITCH + c4 * 4] = v;
        }
    }
    __syncthreads();

    // micro-tile: 2 rows x 8 cols (4 f32x2 pairs). lanes span cols ->
    // A-reads are 2-address broadcasts within a warp.
    const int colg = tid & 15, rowg = tid >> 4;        // rowg 0..31
    const int r0 = rowg * 2, c0 = colg * 8;

    // ---- three intra GEMMs: E_r = relu([self || agg_r] @ W_r), overwrite agg_r ----
    #pragma unroll 1
    for (int rel = 0; rel < 3; rel++) {
        const float* W = (rel == 0) ? Wi1 : (rel == 1) ? Wi2 : Wi3;
        unsigned long long acc[2][4];
        #pragma unroll
        for (int i = 0; i < 2; i++)
            #pragma unroll
            for (int j = 0; j < 4; j++) acc[i][j] = 0ull;

        float4 wreg = __ldg((const float4*)W + tid);   // 512 thr x float4 = 16x128
        #pragma unroll 1
        for (int ck = 0; ck < 16; ck++) {              // 16 chunks of K=16
            float* buf = sWbuf[ck & 1];
            *(float4*)&buf[tid * 4] = wreg;
            __syncthreads();
            if (ck < 15) wreg = __ldg((const float4*)(W + (ck + 1) * 16 * 128) + tid);
            int kk = ck * 16;
            const float* A = (kk < 128) ? (sSelf + r0 * APITCH + kk)
                                        : (sAggs[rel] + r0 * APITCH + (kk - 128));
            mma_chunk(A, buf, c0, acc);
        }
        __syncthreads();   // all reads of agg_r done before overwrite
        #pragma unroll
        for (int i = 0; i < 2; i++)
            #pragma unroll
            for (int j = 0; j < 4; j++) {
                float x, y;
                upk2(acc[i][j], x, y);
                float2 v = make_float2(fmaxf(x, 0.f), fmaxf(y, 0.f));
                *(float2*)&sAggs[rel][(r0 + i) * APITCH + c0 + 2 * j] = v;
            }
        __syncthreads();
    }

    // ---- comb GEMM: relu([self||E1||E2||E3] @ Wc), write transposed [128, B] ----
    unsigned long long acc[2][4];
    #pragma unroll
    for (int i = 0; i < 2; i++)
        #pragma unroll
        for (int j = 0; j < 4; j++) acc[i][j] = 0ull;

    float4 wreg = __ldg((const float4*)Wc + tid);
    #pragma unroll 1
    for (int ck = 0; ck < 32; ck++) {                  // 32 chunks of K=16
        float* buf = sWbuf[ck & 1];
        *(float4*)&buf[tid * 4] = wreg;
        __syncthreads();
        if (ck < 31) wreg = __ldg((const float4*)(Wc + (ck + 1) * 16 * 128) + tid);
        int kk = ck * 16;
        const float* A;
        if (kk < 128) A = sSelf + r0 * APITCH + kk;
        else          A = sAggs[(kk - 128) >> 7] + r0 * APITCH + ((kk - 128) & 127);
        mma_chunk(A, buf, c0, acc);
    }
    // unpack, relu, transpose-store: 2 consecutive rows per column -> float2
    float fo[2][8];
    #pragma unroll
    for (int i = 0; i < 2; i++)
        #pragma unroll
        for (int j = 0; j < 4; j++)
            upk2(acc[i][j], fo[i][2 * j], fo[i][2 * j + 1]);
    #pragma unroll
    for (int jj = 0; jj < 8; jj++) {
        float2 v = make_float2(fmaxf(fo[0][jj], 0.f), fmaxf(fo[1][jj], 0.f));
        *(float2*)(out + (long)(c0 + jj) * BATCH + bm + r0) = v;
    }
}

// ---------------- launch ----------------
extern "C" void kernel_launch(void* const* d_in, const int* in_sizes, int n_in,
                              void* d_out, int out_size) {
    const float* feat  = (const float*)d_in[0];
    const float* Wclf  = (const float*)d_in[1];
    const float* bclf  = (const float*)d_in[2];
    const float* Wi1   = (const float*)d_in[3];
    const float* Wi2   = (const float*)d_in[4];
    const float* Wi3   = (const float*)d_in[5];
    const float* Wc    = (const float*)d_in[6];
    const int*   nodes = (const int*)d_in[7];
    const int*   n1    = (const int*)d_in[8];
    const int*   n2    = (const int*)d_in[9];
    const int*   n3    = (const int*)d_in[10];

    float* out    = (float*)d_out;
    float* out_cs = out + (long)EMB * BATCH;   // center_scores after combined

    // B first (independent of A) so the ncu capture lands on B or C
    dim3 gridB(BATCH, 3);
    agg_kernel<<<gridB, 128>>>(feat, Wclf, bclf, nodes, n1, n2, n3);

    self_score_kernel<<<BATCH / 8, 256>>>(feat, Wclf, bclf, nodes, out_cs);

    int smemC = (4 * 64 * APITCH + 2 * 16 * 128) * sizeof(float);  // ~151 KB
    cudaFuncSetAttribute(fused_gemm_kernel,
                         cudaFuncAttributeMaxDynamicSharedMemorySize, smemC);
    fused_gemm_kernel<<<BATCH / 64, 512, smemC>>>(Wi1, Wi2, Wi3, Wc, out);
}

// round 12
// speedup vs baseline: 1.2829x; 1.2829x over previous
#include <cuda_runtime.h>
#include <cstdint>

#define BATCH   8192
#define FEAT    128
#define DEG     32
#define KSEL    16
#define EMB     128

// ---------------- scratch (static device arrays; no allocation) ----------------
__device__ float g_xbuf[BATCH * FEAT];          // self feats   [B,128]
__device__ float g_agg [3 * BATCH * FEAT];      // agg feats -> overwritten by E_r

// ---------------- f32x2 packed-FMA helpers (Blackwell FFMA2 via PTX) ----------------
__device__ __forceinline__ unsigned long long pk2(float x, float y) {
    unsigned int xu = __float_as_uint(x), yu = __float_as_uint(y);
    unsigned long long r;
    asm("mov.b64 %0, {%1, %2};" : "=l"(r) : "r"(xu), "r"(yu));
    return r;
}
__device__ __forceinline__ void upk2(unsigned long long v, float& x, float& y) {
    unsigned int lo, hi;
    asm("mov.b64 {%0, %1}, %2;" : "=r"(lo), "=r"(hi) : "l"(v));
    x = __uint_as_float(lo);
    y = __uint_as_float(hi);
}
__device__ __forceinline__ void ffma2(unsigned long long& d,
                                      unsigned long long a,
                                      unsigned long long b) {
    asm("fma.rn.f32x2 %0, %1, %2, %0;" : "+l"(d) : "l"(a), "l"(b));
}

// ---------------- Kernel B (launched FIRST): gather + score + top-K + mean ----------------
// One block per (b, rel), 128 threads. Rows live in REGISTERS end-to-end.
// Measured R11: 69 us @ 67.5% DRAM — near traffic floor, unchanged.
__global__ __launch_bounds__(128) void agg_kernel(const float* __restrict__ feat,
                                                  const float* __restrict__ Wclf,
                                                  const float* __restrict__ bclf,
                                                  const int*   __restrict__ nodes,
                                                  const int*   __restrict__ n1,
                                                  const int*   __restrict__ n2,
                                                  const int*   __restrict__ n3) {
    const int b   = blockIdx.x;
    const int rel = blockIdx.y;
    const int* nb = (rel == 0) ? n1 : (rel == 1) ? n2 : n3;

    __shared__ __align__(16) float spart[4][132];   // STS.128 target -> 16B align
    __shared__ float    sscore[DEG];
    __shared__ float    scs0;
    __shared__ unsigned smask;

    const int t = threadIdx.x;
    const int w = t >> 5, l = t & 31;

    float w00 = __ldg(Wclf + 8 * l);
    float w01 = __ldg(Wclf + 8 * l + 2);
    float w02 = __ldg(Wclf + 8 * l + 4);
    float w03 = __ldg(Wclf + 8 * l + 6);
    float bias0 = __ldg(bclf);

    int nidx[8];
    #pragma unroll
    for (int r = 0; r < 8; r++)
        nidx[r] = __ldg(nb + b * DEG + w + 4 * r);
    float4 cf;
    if (w == 0) {
        long cb = (long)__ldg(nodes + b) * FEAT;
        cf = __ldg((const float4*)(feat + cb) + l);
    }
    float4 f[8];
    #pragma unroll
    for (int r = 0; r < 8; r++)
        f[r] = __ldg((const float4*)(feat + (long)nidx[r] * FEAT) + l);

    float p[8];
    #pragma unroll
    for (int r = 0; r < 8; r++)
        p[r] = f[r].x * w00 + f[r].y * w01 + f[r].z * w02 + f[r].w * w03;
    #pragma unroll
    for (int o = 16; o; o >>= 1) {
        #pragma unroll
        for (int r = 0; r < 8; r++)
            p[r] += __shfl_xor_sync(0xffffffffu, p[r], o);
    }
    if (l == 0) {
        #pragma unroll
        for (int r = 0; r < 8; r++)
            sscore[w + 4 * r] = p[r] + bias0;
    }
    if (w == 0) {
        float pc = cf.x * w00 + cf.y * w01 + cf.z * w02 + cf.w * w03;
        #pragma unroll
        for (int o = 16; o; o >>= 1) pc += __shfl_xor_sync(0xffffffffu, pc, o);
        if (l == 0) scs0 = pc + bias0;
    }
    __syncthreads();

    // rank select: K smallest |score - cs0|, stable lower-index tiebreak
    if (t < DEG) {
        float cs0 = scs0;
        float di = fabsf(sscore[t] - cs0);
        int rank = 0;
        #pragma unroll
        for (int j = 0; j < DEG; j++) {
            float dj = fabsf(sscore[j] - cs0);
            rank += (dj < di) || (dj == di && j < t);
        }
        unsigned m = __ballot_sync(0xffffffffu, rank < KSEL);
        if (t == 0) smask = m;
    }
    __syncthreads();

    const unsigned m = smask;
    float4 acc = make_float4(0.f, 0.f, 0.f, 0.f);
    #pragma unroll
    for (int r = 0; r < 8; r++) {
        if (m & (1u << (w + 4 * r))) {
            acc.x += f[r].x; acc.y += f[r].y; acc.z += f[r].z; acc.w += f[r].w;
        }
    }
    *(float4*)&spart[w][4 * l] = acc;
    __syncthreads();

    float s = spart[0][t] + spart[1][t] + spart[2][t] + spart[3][t];
    g_agg[((long)rel * BATCH + b) * FEAT + t] = s * (1.0f / KSEL);
}

// ---------------- Kernel A: self gather + center scores ----------------
__global__ __launch_bounds__(256) void self_score_kernel(const float* __restrict__ feat,
                                                         const float* __restrict__ Wclf,
                                                         const float* __restrict__ bclf,
                                                         const int*   __restrict__ nodes,
                                                         float* __restrict__ out_cs) {
    int wg = threadIdx.x >> 5, l = threadIdx.x & 31;
    int b = blockIdx.x * 8 + wg;
    long base = (long)__ldg(nodes + b) * FEAT;
    float4 f = __ldg((const float4*)(feat + base) + l);
    *(float4*)(g_xbuf + b * FEAT + 4 * l) = f;
    float4 wAB0 = __ldg((const float4*)Wclf + 2 * l);
    float4 wAB1 = __ldg((const float4*)Wclf + 2 * l + 1);
    float p0 = f.x * wAB0.x + f.y * wAB0.z + f.z * wAB1.x + f.w * wAB1.z;
    float p1 = f.x * wAB0.y + f.y * wAB0.w + f.z * wAB1.y + f.w * wAB1.w;
    #pragma unroll
    for (int o = 16; o; o >>= 1) {
        p0 += __shfl_xor_sync(0xffffffffu, p0, o);
        p1 += __shfl_xor_sync(0xffffffffu, p1, o);
    }
    if (l == 0) {
        out_cs[b * 2]     = p0 + __ldg(bclf);
        out_cs[b * 2 + 1] = p1 + __ldg(bclf + 1);
    }
}

// ================= GEMM stage, split for occupancy (2 blocks/SM) =================

#define APITCH 132   // smem row pitch (floats), float4 slots stay 16B-aligned

// 4-row x 8-col micro-tile chunk: 32 FMA per 32B of B -> FFMA2-bound, smem ~50%
__device__ __forceinline__ void mma_chunk4(const float* __restrict__ A,
                                           const float* __restrict__ sW,
                                           int c0, unsigned long long acc[4][4]) {
    #pragma unroll
    for (int q = 0; q < 4; q++) {
        float4 a0 = *(const float4*)&A[0 * APITCH + 4 * q];
        float4 a1 = *(const float4*)&A[1 * APITCH + 4 * q];
        float4 a2 = *(const float4*)&A[2 * APITCH + 4 * q];
        float4 a3 = *(const float4*)&A[3 * APITCH + 4 * q];
        float av0[4] = {a0.x, a0.y, a0.z, a0.w};
        float av1[4] = {a1.x, a1.y, a1.z, a1.w};
        float av2[4] = {a2.x, a2.y, a2.z, a2.w};
        float av3[4] = {a3.x, a3.y, a3.z, a3.w};
        #pragma unroll
        for (int k = 0; k < 4; k++) {
            int k2 = 4 * q + k;
            ulonglong2 b01 = *(const ulonglong2*)&sW[k2 * 128 + c0];
            ulonglong2 b23 = *(const ulonglong2*)&sW[k2 * 128 + c0 + 4];
            unsigned long long ap;
            ap = pk2(av0[k], av0[k]);
            ffma2(acc[0][0], ap, b01.x); ffma2(acc[0][1], ap, b01.y);
            ffma2(acc[0][2], ap, b23.x); ffma2(acc[0][3], ap, b23.y);
            ap = pk2(av1[k], av1[k]);
            ffma2(acc[1][0], ap, b01.x); ffma2(acc[1][1], ap, b01.y);
            ffma2(acc[1][2], ap, b23.x); ffma2(acc[1][3], ap, b23.y);
            ap = pk2(av2[k], av2[k]);
            ffma2(acc[2][0], ap, b01.x); ffma2(acc[2][1], ap, b01.y);
            ffma2(acc[2][2], ap, b23.x); ffma2(acc[2][3], ap, b23.y);
            ap = pk2(av3[k], av3[k]);
            ffma2(acc[3][0], ap, b01.x); ffma2(acc[3][1], ap, b01.y);
            ffma2(acc[3][2], ap, b23.x); ffma2(acc[3][3], ap, b23.y);
        }
    }
}

// 2-row x 8-col variant (comb kernel, BM=32)
__device__ __forceinline__ void mma_chunk2(const float* __restrict__ A,
                                           const float* __restrict__ sW,
                                           int c0, unsigned long long acc[2][4]) {
    #pragma unroll
    for (int q = 0; q < 4; q++) {
        float4 a0 = *(const float4*)&A[0 * APITCH + 4 * q];
        float4 a1 = *(const float4*)&A[1 * APITCH + 4 * q];
        float av0[4] = {a0.x, a0.y, a0.z, a0.w};
        float av1[4] = {a1.x, a1.y, a1.z, a1.w};
        #pragma unroll
        for (int k = 0; k < 4; k++) {
            int k2 = 4 * q + k;
            ulonglong2 b01 = *(const ulonglong2*)&sW[k2 * 128 + c0];
            ulonglong2 b23 = *(const ulonglong2*)&sW[k2 * 128 + c0 + 4];
            unsigned long long ap;
            ap = pk2(av0[k], av0[k]);
            ffma2(acc[0][0], ap, b01.x); ffma2(acc[0][1], ap, b01.y);
            ffma2(acc[0][2], ap, b23.x); ffma2(acc[0][3], ap, b23.y);
            ap = pk2(av1[k], av1[k]);
            ffma2(acc[1][0], ap, b01.x); ffma2(acc[1][1], ap, b01.y);
            ffma2(acc[1][2], ap, b23.x); ffma2(acc[1][3], ap, b23.y);
        }
    }
}

// ---------------- Kernel C1: intra GEMMs. grid (128, 3), 256 thr, 2 blocks/SM ----------------
// E_rel = relu([self || agg_rel] @ W_rel) written IN PLACE over g_agg rows.
__global__ __launch_bounds__(256, 2) void intra_kernel(const float* __restrict__ Wi1,
                                                       const float* __restrict__ Wi2,
                                                       const float* __restrict__ Wi3) {
    extern __shared__ __align__(16) float smem[];
    float* sSelf = smem;                       // 64*APITCH
    float* sAgg  = smem + 64 * APITCH;         // 64*APITCH
    float* sWb0  = smem + 2 * 64 * APITCH;     // 16*128 double buffer
    float* sWb1  = sWb0 + 16 * 128;
    float* sWbuf[2] = {sWb0, sWb1};

    const int tid = threadIdx.x;
    const int bm  = blockIdx.x * 64;
    const int rel = blockIdx.y;
    const float* W = (rel == 0) ? Wi1 : (rel == 1) ? Wi2 : Wi3;

    // load tiles: 8 float4 per thread each
    #pragma unroll
    for (int i = 0; i < 8; i++) {
        int e = tid + i * 256;
        int row = e >> 5, c4 = e & 31;
        float4 v = __ldg((const float4*)(g_xbuf + (long)(bm + row) * FEAT) + c4);
        *(float4*)&sSelf[row * APITCH + c4 * 4] = v;
    }
    #pragma unroll
    for (int i = 0; i < 8; i++) {
        int e = tid + i * 256;
        int row = e >> 5, c4 = e & 31;
        float4 v = __ldg((const float4*)(g_agg + ((long)rel * BATCH + bm + row) * FEAT) + c4);
        *(float4*)&sAgg[row * APITCH + c4 * 4] = v;
    }
    __syncthreads();

    const int colg = tid & 15, rowg = tid >> 4;   // 16 x 16
    const int r0 = rowg * 4, c0 = colg * 8;

    unsigned long long acc[4][4];
    #pragma unroll
    for (int i = 0; i < 4; i++)
        #pragma unroll
        for (int j = 0; j < 4; j++) acc[i][j] = 0ull;

    // W chunk = 16x128 floats = 512 float4; 256 thr -> 2 each. Double-buffered.
    float4 w0 = __ldg((const float4*)W + tid);
    float4 w1 = __ldg((const float4*)W + tid + 256);
    #pragma unroll 1
    for (int ck = 0; ck < 16; ck++) {
        float* buf = sWbuf[ck & 1];
        *(float4*)&buf[tid * 4]         = w0;
        *(float4*)&buf[(tid + 256) * 4] = w1;
        __syncthreads();
        if (ck < 15) {
            w0 = __ldg((const float4*)(W + (ck + 1) * 16 * 128) + tid);
            w1 = __ldg((const float4*)(W + (ck + 1) * 16 * 128) + tid + 256);
        }
        int kk = ck * 16;
        const float* A = (kk < 128) ? (sSelf + r0 * APITCH + kk)
                                    : (sAgg + r0 * APITCH + (kk - 128));
        mma_chunk4(A, buf, c0, acc);
    }

    // relu + write E in place over g_agg (this block owns these rows)
    #pragma unroll
    for (int i = 0; i < 4; i++)
        #pragma unroll
        for (int j = 0; j < 4; j++) {
            float x, y;
            upk2(acc[i][j], x, y);
            float2 v = make_float2(fmaxf(x, 0.f), fmaxf(y, 0.f));
            *(float2*)(g_agg + ((long)rel * BATCH + bm + r0 + i) * FEAT + c0 + 2 * j) = v;
        }
}

// ---------------- Kernel C2: comb GEMM. 256 blocks, BM=32, 256 thr, 2 blocks/SM ----------------
// out = relu([self||E1||E2||E3] @ Wc) stored transposed [128, B].
__global__ __launch_bounds__(256, 2) void comb_kernel(const float* __restrict__ Wc,
                                                      float* __restrict__ out) {
    extern __shared__ __align__(16) float smem[];
    float* sT[4];
    sT[0] = smem;                          // self 32*APITCH
    sT[1] = smem + 32 * APITCH;            // E1
    sT[2] = smem + 2 * 32 * APITCH;        // E2
    sT[3] = smem + 3 * 32 * APITCH;        // E3
    float* sWb0 = smem + 4 * 32 * APITCH;  // 16*128 double buffer
    float* sWb1 = sWb0 + 16 * 128;
    float* sWbuf[2] = {sWb0, sWb1};

    const int tid = threadIdx.x;
    const int bm  = blockIdx.x * 32;

    // each tile: 32 rows x 32 float4 = 1024 f4; 4 per thread
    #pragma unroll
    for (int i = 0; i < 4; i++) {
        int e = tid + i * 256;
        int row = e >> 5, c4 = e & 31;
        float4 v = __ldg((const float4*)(g_xbuf + (long)(bm + row) * FEAT) + c4);
        *(float4*)&sT[0][row * APITCH + c4 * 4] = v;
    }
    #pragma unroll
    for (int rel = 0; rel < 3; rel++) {
        #pragma unroll
        for (int i = 0; i < 4; i++) {
            int e = tid + i * 256;
            int row = e >> 5, c4 = e & 31;
            float4 v = __ldg((const float4*)(g_agg + ((long)rel * BATCH + bm + row) * FEAT) + c4);
            *(float4*)&sT[rel + 1][row * APITCH + c4 * 4] = v;
        }
    }
    __syncthreads();

    const int colg = tid & 15, rowg = tid >> 4;   // 16 x 16
    const int r0 = rowg * 2, c0 = colg * 8;

    unsigned long long acc[2][4];
    #pragma unroll
    for (int i = 0; i < 2; i++)
        #pragma unroll
        for (int j = 0; j < 4; j++) acc[i][j] = 0ull;

    float4 w0 = __ldg((const float4*)Wc + tid);
    float4 w1 = __ldg((const float4*)Wc + tid + 256);
    #pragma unroll 1
    for (int ck = 0; ck < 32; ck++) {
        float* buf = sWbuf[ck & 1];
        *(float4*)&buf[tid * 4]         = w0;
        *(float4*)&buf[(tid + 256) * 4] = w1;
        __syncthreads();
        if (ck < 31) {
            w0 = __ldg((const float4*)(Wc + (ck + 1) * 16 * 128) + tid);
            w1 = __ldg((const float4*)(Wc + (ck + 1) * 16 * 128) + tid + 256);
        }
        int kk = ck * 16;
        const float* A = sT[kk >> 7] + r0 * APITCH + (kk & 127);
        mma_chunk2(A, buf, c0, acc);
    }

    float fo[2][8];
    #pragma unroll
    for (int i = 0; i < 2; i++)
        #pragma unroll
        for (int j = 0; j < 4; j++)
            upk2(acc[i][j], fo[i][2 * j], fo[i][2 * j + 1]);
    #pragma unroll
    for (int jj = 0; jj < 8; jj++) {
        float2 v = make_float2(fmaxf(fo[0][jj], 0.f), fmaxf(fo[1][jj], 0.f));
        *(float2*)(out + (long)(c0 + jj) * BATCH + bm + r0) = v;
    }
}

// ---------------- launch ----------------
extern "C" void kernel_launch(void* const* d_in, const int* in_sizes, int n_in,
                              void* d_out, int out_size) {
    const float* feat  = (const float*)d_in[0];
    const float* Wclf  = (const float*)d_in[1];
    const float* bclf  = (const float*)d_in[2];
    const float* Wi1   = (const float*)d_in[3];
    const float* Wi2   = (const float*)d_in[4];
    const float* Wi3   = (const float*)d_in[5];
    const float* Wc    = (const float*)d_in[6];
    const int*   nodes = (const int*)d_in[7];
    const int*   n1    = (const int*)d_in[8];
    const int*   n2    = (const int*)d_in[9];
    const int*   n3    = (const int*)d_in[10];

    float* out    = (float*)d_out;
    float* out_cs = out + (long)EMB * BATCH;   // center_scores after combined

    dim3 gridB(BATCH, 3);
    agg_kernel<<<gridB, 128>>>(feat, Wclf, bclf, nodes, n1, n2, n3);

    self_score_kernel<<<BATCH / 8, 256>>>(feat, Wclf, bclf, nodes, out_cs);

    int smemI = (2 * 64 * APITCH + 2 * 16 * 128) * sizeof(float);  // ~84 KB
    cudaFuncSetAttribute(intra_kernel,
                         cudaFuncAttributeMaxDynamicSharedMemorySize, smemI);
    dim3 gridI(BATCH / 64, 3);
    intra_kernel<<<gridI, 256, smemI>>>(Wi1, Wi2, Wi3);

    int smemC = (4 * 32 * APITCH + 2 * 16 * 128) * sizeof(float);  // ~84 KB
    cudaFuncSetAttribute(comb_kernel,
                         cudaFuncAttributeMaxDynamicSharedMemorySize, smemC);
    comb_kernel<<<BATCH / 32, 256, smemC>>>(Wc, out);
}

// round 13
// speedup vs baseline: 1.7970x; 1.4007x over previous
#include <cuda_runtime.h>
#include <cstdint>

#define BATCH   8192
#define FEAT    128
#define DEG     32
#define KSEL    16
#define EMB     128

// ---------------- scratch (static device arrays; no allocation) ----------------
__device__ float g_xbuf[BATCH * FEAT];          // self feats   [B,128]
__device__ float g_agg [3 * BATCH * FEAT];      // agg feats -> overwritten by E_r

// ---------------- f32x2 packed-FMA helpers ----------------
__device__ __forceinline__ unsigned long long pk2(float x, float y) {
    unsigned int xu = __float_as_uint(x), yu = __float_as_uint(y);
    unsigned long long r;
    asm("mov.b64 %0, {%1, %2};" : "=l"(r) : "r"(xu), "r"(yu));
    return r;
}
__device__ __forceinline__ void upk2(unsigned long long v, float& x, float& y) {
    unsigned int lo, hi;
    asm("mov.b64 {%0, %1}, %2;" : "=r"(lo), "=r"(hi) : "l"(v));
    x = __uint_as_float(lo);
    y = __uint_as_float(hi);
}
__device__ __forceinline__ void ffma2(unsigned long long& d,
                                      unsigned long long a,
                                      unsigned long long b) {
    asm("fma.rn.f32x2 %0, %1, %2, %0;" : "+l"(d) : "l"(a), "l"(b));
}

// ---------------- Kernel B: gather + score + top-K + mean (69us, DRAM-bound, keep) ----------------
__global__ __launch_bounds__(128) void agg_kernel(const float* __restrict__ feat,
                                                  const float* __restrict__ Wclf,
                                                  const float* __restrict__ bclf,
                                                  const int*   __restrict__ nodes,
                                                  const int*   __restrict__ n1,
                                                  const int*   __restrict__ n2,
                                                  const int*   __restrict__ n3) {
    const int b   = blockIdx.x;
    const int rel = blockIdx.y;
    const int* nb = (rel == 0) ? n1 : (rel == 1) ? n2 : n3;

    __shared__ __align__(16) float spart[4][132];
    __shared__ float    sscore[DEG];
    __shared__ float    scs0;
    __shared__ unsigned smask;

    const int t = threadIdx.x;
    const int w = t >> 5, l = t & 31;

    float w00 = __ldg(Wclf + 8 * l);
    float w01 = __ldg(Wclf + 8 * l + 2);
    float w02 = __ldg(Wclf + 8 * l + 4);
    float w03 = __ldg(Wclf + 8 * l + 6);
    float bias0 = __ldg(bclf);

    int nidx[8];
    #pragma unroll
    for (int r = 0; r < 8; r++)
        nidx[r] = __ldg(nb + b * DEG + w + 4 * r);
    float4 cf;
    if (w == 0) {
        long cb = (long)__ldg(nodes + b) * FEAT;
        cf = __ldg((const float4*)(feat + cb) + l);
    }
    float4 f[8];
    #pragma unroll
    for (int r = 0; r < 8; r++)
        f[r] = __ldg((const float4*)(feat + (long)nidx[r] * FEAT) + l);

    float p[8];
    #pragma unroll
    for (int r = 0; r < 8; r++)
        p[r] = f[r].x * w00 + f[r].y * w01 + f[r].z * w02 + f[r].w * w03;
    #pragma unroll
    for (int o = 16; o; o >>= 1) {
        #pragma unroll
        for (int r = 0; r < 8; r++)
            p[r] += __shfl_xor_sync(0xffffffffu, p[r], o);
    }
    if (l == 0) {
        #pragma unroll
        for (int r = 0; r < 8; r++)
            sscore[w + 4 * r] = p[r] + bias0;
    }
    if (w == 0) {
        float pc = cf.x * w00 + cf.y * w01 + cf.z * w02 + cf.w * w03;
        #pragma unroll
        for (int o = 16; o; o >>= 1) pc += __shfl_xor_sync(0xffffffffu, pc, o);
        if (l == 0) scs0 = pc + bias0;
    }
    __syncthreads();

    if (t < DEG) {
        float cs0 = scs0;
        float di = fabsf(sscore[t] - cs0);
        int rank = 0;
        #pragma unroll
        for (int j = 0; j < DEG; j++) {
            float dj = fabsf(sscore[j] - cs0);
            rank += (dj < di) || (dj == di && j < t);
        }
        unsigned m = __ballot_sync(0xffffffffu, rank < KSEL);
        if (t == 0) smask = m;
    }
    __syncthreads();

    const unsigned m = smask;
    float4 acc = make_float4(0.f, 0.f, 0.f, 0.f);
    #pragma unroll
    for (int r = 0; r < 8; r++) {
        if (m & (1u << (w + 4 * r))) {
            acc.x += f[r].x; acc.y += f[r].y; acc.z += f[r].z; acc.w += f[r].w;
        }
    }
    *(float4*)&spart[w][4 * l] = acc;
    __syncthreads();

    float s = spart[0][t] + spart[1][t] + spart[2][t] + spart[3][t];
    g_agg[((long)rel * BATCH + b) * FEAT + t] = s * (1.0f / KSEL);
}

// ---------------- Kernel A: self gather + center scores ----------------
__global__ __launch_bounds__(256) void self_score_kernel(const float* __restrict__ feat,
                                                         const float* __restrict__ Wclf,
                                                         const float* __restrict__ bclf,
                                                         const int*   __restrict__ nodes,
                                                         float* __restrict__ out_cs) {
    int wg = threadIdx.x >> 5, l = threadIdx.x & 31;
    int b = blockIdx.x * 8 + wg;
    long base = (long)__ldg(nodes + b) * FEAT;
    float4 f = __ldg((const float4*)(feat + base) + l);
    *(float4*)(g_xbuf + b * FEAT + 4 * l) = f;
    float4 wAB0 = __ldg((const float4*)Wclf + 2 * l);
    float4 wAB1 = __ldg((const float4*)Wclf + 2 * l + 1);
    float p0 = f.x * wAB0.x + f.y * wAB0.z + f.z * wAB1.x + f.w * wAB1.z;
    float p1 = f.x * wAB0.y + f.y * wAB0.w + f.z * wAB1.y + f.w * wAB1.w;
    #pragma unroll
    for (int o = 16; o; o >>= 1) {
        p0 += __shfl_xor_sync(0xffffffffu, p0, o);
        p1 += __shfl_xor_sync(0xffffffffu, p1, o);
    }
    if (l == 0) {
        out_cs[b * 2]     = p0 + __ldg(bclf);
        out_cs[b * 2 + 1] = p1 + __ldg(bclf + 1);
    }
}

// ================= GEMM stage: 8x8 micro-tile, A streamed from gmem =================
// Per thread per 16-K chunk: 512B B-reads + 512B A-reads per 512 FFMA2 lane-ops
// -> smem crossbar ~50% of FMA issue (was 250% with 2x8 tile). smem 24KB/block.

// mma over one K=16 chunk; A points at this thread's row base (pitch 16 floats)
__device__ __forceinline__ void mma8(const float* __restrict__ A,
                                     const float* __restrict__ sW,
                                     int c0, unsigned long long acc[8][4]) {
    #pragma unroll
    for (int q = 0; q < 4; q++) {
        float4 av[8];
        #pragma unroll
        for (int i = 0; i < 8; i++)
            av[i] = *(const float4*)&A[i * 16 + 4 * q];
        #pragma unroll
        for (int k = 0; k < 4; k++) {
            int k2 = 4 * q + k;
            ulonglong2 b01 = *(const ulonglong2*)&sW[k2 * 128 + c0];
            ulonglong2 b23 = *(const ulonglong2*)&sW[k2 * 128 + c0 + 4];
            #pragma unroll
            for (int i = 0; i < 8; i++) {
                float a = (k == 0) ? av[i].x : (k == 1) ? av[i].y
                        : (k == 2) ? av[i].z : av[i].w;
                unsigned long long ap = pk2(a, a);
                ffma2(acc[i][0], ap, b01.x);
                ffma2(acc[i][1], ap, b01.y);
                ffma2(acc[i][2], ap, b23.x);
                ffma2(acc[i][3], ap, b23.y);
            }
        }
    }
}

// W chunk (16x128 floats = 512 float4): 128 thr x 4 float4
__device__ __forceinline__ void ldW(const float* __restrict__ W, int kk, int tid,
                                    float4 w[4]) {
    #pragma unroll
    for (int i = 0; i < 4; i++)
        w[i] = __ldg((const float4*)(W + kk * 128) + tid + i * 128);
}
__device__ __forceinline__ void stW(float* __restrict__ sW, int tid, const float4 w[4]) {
    #pragma unroll
    for (int i = 0; i < 4; i++)
        *(float4*)&sW[(tid + i * 128) * 4] = w[i];
}
// A chunk (64 rows x 16 cols from row-major src, row stride FEAT): 128 thr x 2 float4
__device__ __forceinline__ void ldA(const float* __restrict__ src, int bm, int kk,
                                    int tid, float4 a[2]) {
    #pragma unroll
    for (int i = 0; i < 2; i++) {
        int e = tid + i * 128;
        int row = e >> 2, c4 = e & 3;
        a[i] = __ldg((const float4*)(src + (long)(bm + row) * FEAT + kk) + c4);
    }
}
__device__ __forceinline__ void stA(float* __restrict__ sA, int tid, const float4 a[2]) {
    #pragma unroll
    for (int i = 0; i < 2; i++) {
        int e = tid + i * 128;
        int row = e >> 2, c4 = e & 3;
        *(float4*)&sA[row * 16 + c4 * 4] = a[i];
    }
}

// ---------------- Kernel C1: intra GEMMs, grid (128, 3), 128 thr ----------------
// E_rel = relu([self || agg_rel] @ W_rel) written in place over g_agg rows.
__global__ __launch_bounds__(128) void intra_kernel(const float* __restrict__ Wi1,
                                                    const float* __restrict__ Wi2,
                                                    const float* __restrict__ Wi3) {
    __shared__ __align__(16) float sW[2][16 * 128];
    __shared__ __align__(16) float sA[2][64 * 16];

    const int tid = threadIdx.x;
    const int bm  = blockIdx.x * 64;
    const int rel = blockIdx.y;
    const float* W = (rel == 0) ? Wi1 : (rel == 1) ? Wi2 : Wi3;
    const float* srcs[2] = {g_xbuf, g_agg + (long)rel * BATCH * FEAT};

    const int colg = tid & 15, rowg = tid >> 4;       // 16 x 8
    const int r0 = rowg * 8, c0 = colg * 8;

    unsigned long long acc[8][4];
    #pragma unroll
    for (int i = 0; i < 8; i++)
        #pragma unroll
        for (int j = 0; j < 4; j++) acc[i][j] = 0ull;

    float4 w[4], a[2];
    ldW(W, 0, tid, w);
    ldA(srcs[0], bm, 0, tid, a);
    #pragma unroll 1
    for (int ck = 0; ck < 16; ck++) {
        float* bw = sW[ck & 1];
        float* ba = sA[ck & 1];
        stW(bw, tid, w);
        stA(ba, tid, a);
        __syncthreads();
        if (ck < 15) {
            int kn = (ck + 1) * 16;
            ldW(W, kn, tid, w);
            ldA(srcs[(ck + 1) >> 3], bm, kn & 127, tid, a);
        }
        mma8(ba + r0 * 16, bw, c0, acc);
        __syncthreads();
    }

    // relu + write E in place (this block owns these g_agg rows)
    #pragma unroll
    for (int i = 0; i < 8; i++) {
        float v[8];
        #pragma unroll
        for (int j = 0; j < 4; j++) upk2(acc[i][j], v[2 * j], v[2 * j + 1]);
        float4 o0 = make_float4(fmaxf(v[0], 0.f), fmaxf(v[1], 0.f),
                                fmaxf(v[2], 0.f), fmaxf(v[3], 0.f));
        float4 o1 = make_float4(fmaxf(v[4], 0.f), fmaxf(v[5], 0.f),
                                fmaxf(v[6], 0.f), fmaxf(v[7], 0.f));
        float* dst = g_agg + ((long)rel * BATCH + bm + r0 + i) * FEAT + c0;
        *(float4*)dst       = o0;
        *(float4*)(dst + 4) = o1;
    }
}

// ---------------- Kernel C2: comb GEMM, 128 blocks, 128 thr ----------------
// out = relu([self||E1||E2||E3] @ Wc) stored transposed [128, B].
__global__ __launch_bounds__(128) void comb_kernel(const float* __restrict__ Wc,
                                                   float* __restrict__ out) {
    __shared__ __align__(16) float sW[2][16 * 128];
    __shared__ __align__(16) float sA[2][64 * 16];

    const int tid = threadIdx.x;
    const int bm  = blockIdx.x * 64;
    const float* srcs[4] = {g_xbuf,
                            g_agg,
                            g_agg + (long)BATCH * FEAT,
                            g_agg + 2L * BATCH * FEAT};

    const int colg = tid & 15, rowg = tid >> 4;
    const int r0 = rowg * 8, c0 = colg * 8;

    unsigned long long acc[8][4];
    #pragma unroll
    for (int i = 0; i < 8; i++)
        #pragma unroll
        for (int j = 0; j < 4; j++) acc[i][j] = 0ull;

    float4 w[4], a[2];
    ldW(Wc, 0, tid, w);
    ldA(srcs[0], bm, 0, tid, a);
    #pragma unroll 1
    for (int ck = 0; ck < 32; ck++) {
        float* bw = sW[ck & 1];
        float* ba = sA[ck & 1];
        stW(bw, tid, w);
        stA(ba, tid, a);
        __syncthreads();
        if (ck < 31) {
            int kn = (ck + 1) * 16;
            ldW(Wc, kn, tid, w);
            ldA(srcs[(ck + 1) >> 3], bm, kn & 127, tid, a);
        }
        mma8(ba + r0 * 16, bw, c0, acc);
        __syncthreads();
    }

    // unpack, relu, transposed store: per col j, 8 consecutive rows -> 2x float4
    float v[8][8];
    #pragma unroll
    for (int i = 0; i < 8; i++)
        #pragma unroll
        for (int j = 0; j < 4; j++) upk2(acc[i][j], v[i][2 * j], v[i][2 * j + 1]);
    #pragma unroll
    for (int j = 0; j < 8; j++) {
        float4 o0 = make_float4(fmaxf(v[0][j], 0.f), fmaxf(v[1][j], 0.f),
                                fmaxf(v[2][j], 0.f), fmaxf(v[3][j], 0.f));
        float4 o1 = make_float4(fmaxf(v[4][j], 0.f), fmaxf(v[5][j], 0.f),
                                fmaxf(v[6][j], 0.f), fmaxf(v[7][j], 0.f));
        float* dst = out + (long)(c0 + j) * BATCH + bm + r0;
        *(float4*)dst       = o0;
        *(float4*)(dst + 4) = o1;
    }
}

// ---------------- launch ----------------
extern "C" void kernel_launch(void* const* d_in, const int* in_sizes, int n_in,
                              void* d_out, int out_size) {
    const float* feat  = (const float*)d_in[0];
    const float* Wclf  = (const float*)d_in[1];
    const float* bclf  = (const float*)d_in[2];
    const float* Wi1   = (const float*)d_in[3];
    const float* Wi2   = (const float*)d_in[4];
    const float* Wi3   = (const float*)d_in[5];
    const float* Wc    = (const float*)d_in[6];
    const int*   nodes = (const int*)d_in[7];
    const int*   n1    = (const int*)d_in[8];
    const int*   n2    = (const int*)d_in[9];
    const int*   n3    = (const int*)d_in[10];

    float* out    = (float*)d_out;
    float* out_cs = out + (long)EMB * BATCH;   // center_scores after combined

    dim3 gridB(BATCH, 3);
    agg_kernel<<<gridB, 128>>>(feat, Wclf, bclf, nodes, n1, n2, n3);

    self_score_kernel<<<BATCH / 8, 256>>>(feat, Wclf, bclf, nodes, out_cs);

    dim3 gridI(BATCH / 64, 3);
    intra_kernel<<<gridI, 128>>>(Wi1, Wi2, Wi3);

    comb_kernel<<<BATCH / 64, 128>>>(Wc, out);
}

// round 15
// speedup vs baseline: 1.9832x; 1.1036x over previous
#include <cuda_runtime.h>
#include <cstdint>

#define BATCH   8192
#define FEAT    128
#define DEG     32
#define KSEL    16
#define EMB     128

// ---------------- scratch (static device arrays; no allocation) ----------------
__device__ float g_xbuf[BATCH * FEAT];          // self feats   [B,128]
__device__ float g_agg [3 * BATCH * FEAT];      // agg feats -> overwritten by E_r

// ---------------- f32x2 packed-FMA helpers ----------------
__device__ __forceinline__ unsigned long long pk2(float x, float y) {
    unsigned int xu = __float_as_uint(x), yu = __float_as_uint(y);
    unsigned long long r;
    asm("mov.b64 %0, {%1, %2};" : "=l"(r) : "r"(xu), "r"(yu));
    return r;
}
__device__ __forceinline__ void upk2(unsigned long long v, float& x, float& y) {
    unsigned int lo, hi;
    asm("mov.b64 {%0, %1}, %2;" : "=r"(lo), "=r"(hi) : "l"(v));
    x = __uint_as_float(lo);
    y = __uint_as_float(hi);
}
__device__ __forceinline__ void ffma2(unsigned long long& d,
                                      unsigned long long a,
                                      unsigned long long b) {
    asm("fma.rn.f32x2 %0, %1, %2, %0;" : "+l"(d) : "l"(a), "l"(b));
}

// ---------------- Kernel B: gather + score + top-K + mean (69us, DRAM-bound, keep) ----------------
__global__ __launch_bounds__(128) void agg_kernel(const float* __restrict__ feat,
                                                  const float* __restrict__ Wclf,
                                                  const float* __restrict__ bclf,
                                                  const int*   __restrict__ nodes,
                                                  const int*   __restrict__ n1,
                                                  const int*   __restrict__ n2,
                                                  const int*   __restrict__ n3) {
    const int b   = blockIdx.x;
    const int rel = blockIdx.y;
    const int* nb = (rel == 0) ? n1 : (rel == 1) ? n2 : n3;

    __shared__ __align__(16) float spart[4][132];
    __shared__ float    sscore[DEG];
    __shared__ float    scs0;
    __shared__ unsigned smask;

    const int t = threadIdx.x;
    const int w = t >> 5, l = t & 31;

    float w00 = __ldg(Wclf + 8 * l);
    float w01 = __ldg(Wclf + 8 * l + 2);
    float w02 = __ldg(Wclf + 8 * l + 4);
    float w03 = __ldg(Wclf + 8 * l + 6);
    float bias0 = __ldg(bclf);

    int nidx[8];
    #pragma unroll
    for (int r = 0; r < 8; r++)
        nidx[r] = __ldg(nb + b * DEG + w + 4 * r);
    float4 cf;
    if (w == 0) {
        long cb = (long)__ldg(nodes + b) * FEAT;
        cf = __ldg((const float4*)(feat + cb) + l);
    }
    float4 f[8];
    #pragma unroll
    for (int r = 0; r < 8; r++)
        f[r] = __ldg((const float4*)(feat + (long)nidx[r] * FEAT) + l);

    float p[8];
    #pragma unroll
    for (int r = 0; r < 8; r++)
        p[r] = f[r].x * w00 + f[r].y * w01 + f[r].z * w02 + f[r].w * w03;
    #pragma unroll
    for (int o = 16; o; o >>= 1) {
        #pragma unroll
        for (int r = 0; r < 8; r++)
            p[r] += __shfl_xor_sync(0xffffffffu, p[r], o);
    }
    if (l == 0) {
        #pragma unroll
        for (int r = 0; r < 8; r++)
            sscore[w + 4 * r] = p[r] + bias0;
    }
    if (w == 0) {
        float pc = cf.x * w00 + cf.y * w01 + cf.z * w02 + cf.w * w03;
        #pragma unroll
        for (int o = 16; o; o >>= 1) pc += __shfl_xor_sync(0xffffffffu, pc, o);
        if (l == 0) scs0 = pc + bias0;
    }
    __syncthreads();

    if (t < DEG) {
        float cs0 = scs0;
        float di = fabsf(sscore[t] - cs0);
        int rank = 0;
        #pragma unroll
        for (int j = 0; j < DEG; j++) {
            float dj = fabsf(sscore[j] - cs0);
            rank += (dj < di) || (dj == di && j < t);
        }
        unsigned m = __ballot_sync(0xffffffffu, rank < KSEL);
        if (t == 0) smask = m;
    }
    __syncthreads();

    const unsigned m = smask;
    float4 acc = make_float4(0.f, 0.f, 0.f, 0.f);
    #pragma unroll
    for (int r = 0; r < 8; r++) {
        if (m & (1u << (w + 4 * r))) {
            acc.x += f[r].x; acc.y += f[r].y; acc.z += f[r].z; acc.w += f[r].w;
        }
    }
    *(float4*)&spart[w][4 * l] = acc;
    __syncthreads();

    float s = spart[0][t] + spart[1][t] + spart[2][t] + spart[3][t];
    g_agg[((long)rel * BATCH + b) * FEAT + t] = s * (1.0f / KSEL);
}

// ---------------- Kernel A: self gather + center scores ----------------
__global__ __launch_bounds__(256) void self_score_kernel(const float* __restrict__ feat,
                                                         const float* __restrict__ Wclf,
                                                         const float* __restrict__ bclf,
                                                         const int*   __restrict__ nodes,
                                                         float* __restrict__ out_cs) {
    int wg = threadIdx.x >> 5, l = threadIdx.x & 31;
    int b = blockIdx.x * 8 + wg;
    long base = (long)__ldg(nodes + b) * FEAT;
    float4 f = __ldg((const float4*)(feat + base) + l);
    *(float4*)(g_xbuf + b * FEAT + 4 * l) = f;
    float4 wAB0 = __ldg((const float4*)Wclf + 2 * l);
    float4 wAB1 = __ldg((const float4*)Wclf + 2 * l + 1);
    float p0 = f.x * wAB0.x + f.y * wAB0.z + f.z * wAB1.x + f.w * wAB1.z;
    float p1 = f.x * wAB0.y + f.y * wAB0.w + f.z * wAB1.y + f.w * wAB1.w;
    #pragma unroll
    for (int o = 16; o; o >>= 1) {
        p0 += __shfl_xor_sync(0xffffffffu, p0, o);
        p1 += __shfl_xor_sync(0xffffffffu, p1, o);
    }
    if (l == 0) {
        out_cs[b * 2]     = p0 + __ldg(bclf);
        out_cs[b * 2 + 1] = p1 + __ldg(bclf + 1);
    }
}

// ================= GEMM stage: 8x8 micro-tile + warpgroup split-K =================
// 256 threads = 2 warpgroups of 128; each group handles half the K-chunks with
// its own double-buffered smem stage -> 2 warps/SMSP hide LDS latency.
// Final: group 1 dumps packed accs to smem, group 0 adds + relu + stores.

#define WCHUNK (16 * 128)   // floats per W chunk
#define ACHUNK (64 * 16)    // floats per A chunk

__device__ __forceinline__ void mma8(const float* __restrict__ A,
                                     const float* __restrict__ sW,
                                     int c0, unsigned long long acc[8][4]) {
    #pragma unroll
    for (int q = 0; q < 4; q++) {
        float4 av[8];
        #pragma unroll
        for (int i = 0; i < 8; i++)
            av[i] = *(const float4*)&A[i * 16 + 4 * q];
        #pragma unroll
        for (int k = 0; k < 4; k++) {
            int k2 = 4 * q + k;
            ulonglong2 b01 = *(const ulonglong2*)&sW[k2 * 128 + c0];
            ulonglong2 b23 = *(const ulonglong2*)&sW[k2 * 128 + c0 + 4];
            #pragma unroll
            for (int i = 0; i < 8; i++) {
                float a = (k == 0) ? av[i].x : (k == 1) ? av[i].y
                        : (k == 2) ? av[i].z : av[i].w;
                unsigned long long ap = pk2(a, a);
                ffma2(acc[i][0], ap, b01.x);
                ffma2(acc[i][1], ap, b01.y);
                ffma2(acc[i][2], ap, b23.x);
                ffma2(acc[i][3], ap, b23.y);
            }
        }
    }
}

__device__ __forceinline__ void ldW(const float* __restrict__ W, int kk, int wt,
                                    float4 w[4]) {
    #pragma unroll
    for (int i = 0; i < 4; i++)
        w[i] = __ldg((const float4*)(W + kk * 128) + wt + i * 128);
}
__device__ __forceinline__ void stW(float* __restrict__ sW, int wt, const float4 w[4]) {
    #pragma unroll
    for (int i = 0; i < 4; i++)
        *(float4*)&sW[(wt + i * 128) * 4] = w[i];
}
__device__ __forceinline__ void ldA(const float* __restrict__ src, int bm, int kk,
                                    int wt, float4 a[2]) {
    #pragma unroll
    for (int i = 0; i < 2; i++) {
        int e = wt + i * 128;
        int row = e >> 2, c4 = e & 3;
        a[i] = __ldg((const float4*)(src + (long)(bm + row) * FEAT + kk) + c4);
    }
}
__device__ __forceinline__ void stA(float* __restrict__ sA, int wt, const float4 a[2]) {
    #pragma unroll
    for (int i = 0; i < 2; i++) {
        int e = wt + i * 128;
        int row = e >> 2, c4 = e & 3;
        *(float4*)&sA[row * 16 + c4 * 4] = a[i];
    }
}

// Shared mainloop body. NCHUNK chunks total, each group runs NCHUNK/2.
// A-source boundaries every 128 K-values: src index = K_offset >> 7.
// smem layout: [W g0 buf0][W g0 buf1][W g1 buf0][W g1 buf1][A x4 same]
// Reduction region reuses the W area (32 KB >= 128thr*64 floats = 32 KB).
template <int NCHUNK, int NSRC>
__device__ __forceinline__ void gemm_splitk(const float* __restrict__ W,
                                            const float* const srcs[NSRC],
                                            int bm, float* smem,
                                            unsigned long long acc[8][4],
                                            int& grp, int& r0, int& c0) {
    const int tid = threadIdx.x;
    grp = tid >> 7;
    const int wt = tid & 127;
    const int colg = wt & 15, rowg = wt >> 4;
    r0 = rowg * 8; c0 = colg * 8;

    float* sWg = smem + grp * 2 * WCHUNK;
    float* sAg = smem + 4 * WCHUNK + grp * 2 * ACHUNK;

    #pragma unroll
    for (int i = 0; i < 8; i++)
        #pragma unroll
        for (int j = 0; j < 4; j++) acc[i][j] = 0ull;

    const int half = NCHUNK / 2;
    const int ck0 = grp * half;
    const int kk0 = ck0 * 16;
    float4 w[4], a[2];
    ldW(W, kk0, wt, w);
    ldA(srcs[kk0 >> 7], bm, kk0 & 127, wt, a);   // src boundary every 128 K
    #pragma unroll 1
    for (int s = 0; s < half; s++) {
        int ck = ck0 + s;
        float* bw = sWg + (s & 1) * WCHUNK;
        float* ba = sAg + (s & 1) * ACHUNK;
        stW(bw, wt, w);
        stA(ba, wt, a);
        __syncthreads();
        if (s < half - 1) {
            int kn = (ck + 1) * 16;
            ldW(W, kn, wt, w);
            ldA(srcs[kn >> 7], bm, kn & 127, wt, a);
        }
        mma8(ba + r0 * 16, bw, c0, acc);
        __syncthreads();
    }

    // cross-group reduction: group 1 dumps, group 0 accumulates.
    float* red = smem;   // 32 KB: slot-major, lane stride 2 floats (no conflicts)
    if (grp == 1) {
        #pragma unroll
        for (int i = 0; i < 8; i++)
            #pragma unroll
            for (int j = 0; j < 4; j++)
                *(unsigned long long*)&red[(i * 4 + j) * 256 + wt * 2] = acc[i][j];
    }
    __syncthreads();
    if (grp == 0) {
        #pragma unroll
        for (int i = 0; i < 8; i++)
            #pragma unroll
            for (int j = 0; j < 4; j++) {
                float x0, y0, x1, y1;
                upk2(acc[i][j], x0, y0);
                upk2(*(const unsigned long long*)&red[(i * 4 + j) * 256 + wt * 2], x1, y1);
                acc[i][j] = pk2(x0 + x1, y0 + y1);
            }
    }
}

// ---------------- Kernel C1: intra GEMMs, grid (128, 3), 256 thr ----------------
__global__ __launch_bounds__(256, 1) void intra_kernel(const float* __restrict__ Wi1,
                                                       const float* __restrict__ Wi2,
                                                       const float* __restrict__ Wi3) {
    extern __shared__ __align__(16) float smem[];
    const int bm  = blockIdx.x * 64;
    const int rel = blockIdx.y;
    const float* W = (rel == 0) ? Wi1 : (rel == 1) ? Wi2 : Wi3;
    const float* srcs[2] = {g_xbuf, g_agg + (long)rel * BATCH * FEAT};

    unsigned long long acc[8][4];
    int grp, r0, c0;
    gemm_splitk<16, 2>(W, srcs, bm, smem, acc, grp, r0, c0);

    if (grp == 0) {
        #pragma unroll
        for (int i = 0; i < 8; i++) {
            float v[8];
            #pragma unroll
            for (int j = 0; j < 4; j++) upk2(acc[i][j], v[2 * j], v[2 * j + 1]);
            float4 o0 = make_float4(fmaxf(v[0], 0.f), fmaxf(v[1], 0.f),
                                    fmaxf(v[2], 0.f), fmaxf(v[3], 0.f));
            float4 o1 = make_float4(fmaxf(v[4], 0.f), fmaxf(v[5], 0.f),
                                    fmaxf(v[6], 0.f), fmaxf(v[7], 0.f));
            float* dst = g_agg + ((long)rel * BATCH + bm + r0 + i) * FEAT + c0;
            *(float4*)dst       = o0;
            *(float4*)(dst + 4) = o1;
        }
    }
}

// ---------------- Kernel C2: comb GEMM, 128 blocks, 256 thr ----------------
__global__ __launch_bounds__(256, 1) void comb_kernel(const float* __restrict__ Wc,
                                                      float* __restrict__ out) {
    extern __shared__ __align__(16) float smem[];
    const int bm = blockIdx.x * 64;
    const float* srcs[4] = {g_xbuf,
                            g_agg,
                            g_agg + (long)BATCH * FEAT,
                            g_agg + 2L * BATCH * FEAT};

    unsigned long long acc[8][4];
    int grp, r0, c0;
    gemm_splitk<32, 4>(Wc, srcs, bm, smem, acc, grp, r0, c0);

    if (grp == 0) {
        float v[8][8];
        #pragma unroll
        for (int i = 0; i < 8; i++)
            #pragma unroll
            for (int j = 0; j < 4; j++) upk2(acc[i][j], v[i][2 * j], v[i][2 * j + 1]);
        #pragma unroll
        for (int j = 0; j < 8; j++) {
            float4 o0 = make_float4(fmaxf(v[0][j], 0.f), fmaxf(v[1][j], 0.f),
                                    fmaxf(v[2][j], 0.f), fmaxf(v[3][j], 0.f));
            float4 o1 = make_float4(fmaxf(v[4][j], 0.f), fmaxf(v[5][j], 0.f),
                                    fmaxf(v[6][j], 0.f), fmaxf(v[7][j], 0.f));
            float* dst = out + (long)(c0 + j) * BATCH + bm + r0;
            *(float4*)dst       = o0;
            *(float4*)(dst + 4) = o1;
        }
    }
}

// ---------------- launch ----------------
extern "C" void kernel_launch(void* const* d_in, const int* in_sizes, int n_in,
                              void* d_out, int out_size) {
    const float* feat  = (const float*)d_in[0];
    const float* Wclf  = (const float*)d_in[1];
    const float* bclf  = (const float*)d_in[2];
    const float* Wi1   = (const float*)d_in[3];
    const float* Wi2   = (const float*)d_in[4];
    const float* Wi3   = (const float*)d_in[5];
    const float* Wc    = (const float*)d_in[6];
    const int*   nodes = (const int*)d_in[7];
    const int*   n1    = (const int*)d_in[8];
    const int*   n2    = (const int*)d_in[9];
    const int*   n3    = (const int*)d_in[10];

    float* out    = (float*)d_out;
    float* out_cs = out + (long)EMB * BATCH;   // center_scores after combined

    dim3 gridB(BATCH, 3);
    agg_kernel<<<gridB, 128>>>(feat, Wclf, bclf, nodes, n1, n2, n3);

    self_score_kernel<<<BATCH / 8, 256>>>(feat, Wclf, bclf, nodes, out_cs);

    int smemG = (4 * WCHUNK + 4 * ACHUNK) * sizeof(float);  // 48 KB
    cudaFuncSetAttribute(intra_kernel,
                         cudaFuncAttributeMaxDynamicSharedMemorySize, smemG);
    cudaFuncSetAttribute(comb_kernel,
                         cudaFuncAttributeMaxDynamicSharedMemorySize, smemG);

    dim3 gridI(BATCH / 64, 3);
    intra_kernel<<<gridI, 256, smemG>>>(Wi1, Wi2, Wi3);

    comb_kernel<<<BATCH / 64, 256, smemG>>>(Wc, out);
}